// round 16
// baseline (speedup 1.0000x reference)
#include <cuda_runtime.h>
#include <math.h>

#define HW   4096
#define NB   8
#define NFC  768
#define NRC  8
#define NP   8

typedef unsigned long long ull;

// ---------------- scratch ----------------
__device__ float g_cpre[NB*NRC*HW];
__device__ float g_car [NB*NRC*HW];
__device__ float g_dn  [NB*HW];
__device__ float g_hp  [NB*HW];
__device__ float g_cs  [NB*HW];
__device__ float g_sf  [NB*HW];
__device__ float g_part[128*8];
__device__ float g_kern[NP*81];

// ---------------- helpers ----------------
__device__ __forceinline__ ull pack2(float lo, float hi){ ull r; asm("mov.b64 %0,{%1,%2};":"=l"(r):"f"(lo),"f"(hi)); return r; }
__device__ __forceinline__ ull fma2(ull a, ull b, ull c){ ull d; asm("fma.rn.f32x2 %0,%1,%2,%3;":"=l"(d):"l"(a),"l"(b),"l"(c)); return d; }
__device__ __forceinline__ ull add2(ull a, ull b){ ull d; asm("add.rn.f32x2 %0,%1,%2;":"=l"(d):"l"(a),"l"(b)); return d; }
__device__ __forceinline__ void unpack2(ull v, float&lo, float&hi){ asm("mov.b64 {%0,%1},%2;":"=f"(lo),"=f"(hi):"l"(v)); }
__device__ __forceinline__ float geluf(float x){ return 0.5f*x*(1.0f+erff(x*0.70710678118654752f)); }
__device__ __forceinline__ float sigmf_(float x){ return 1.0f/(1.0f+__expf(-x)); }

__device__ __constant__ float c_ca[8] = {1.0f, 0.707106781f, 6.12323426e-17f, -0.707106781f,
                                         -1.0f, -0.707106781f, -1.83697015e-16f, 0.707106781f};
__device__ __constant__ float c_sa[8] = {0.0f, 0.707106781f, 1.0f, 0.707106781f,
                                         1.22464685e-16f, -0.707106781f, -1.0f, -0.707106781f};

// ---------------- K1: 768->8 1x1 conv + gelu; warp-granular 8-way K-split (2 px/thread) ----------------
__global__ __launch_bounds__(256) void k1_gemm(const float* __restrict__ fm,
                                               const float* __restrict__ w,
                                               const float* __restrict__ bv,
                                               const float* __restrict__ pdelta){
    extern __shared__ char dsmc[];
    float* wsf = (float*)dsmc;                 // 6144 floats, c-major [c][r]
    ull*   part = (ull*)(dsmc + 24576);        // 32*65 ull
    __shared__ float ridgeS[NP*81];
    for (int i = threadIdx.x; i < NFC*NRC; i += 256){
        int c = i >> 3, r = i & 7;
        wsf[i] = w[r*NFC + c];
    }
    __syncthreads();
    int blk = blockIdx.x;                      // 512 blocks
    int b = blk >> 6, pg = blk & 63;
    int wp = threadIdx.x >> 5, lane = threadIdx.x & 31;
    int p = (pg*32 + lane) << 1;
    const float* x = fm + (size_t)b*NFC*HW + (size_t)(wp*96)*HW + p;
    const float* wc0 = wsf + wp*96*8;
    ull acc[NRC];
    #pragma unroll
    for (int r = 0; r < NRC; r++) acc[r] = 0ull;
    #pragma unroll 8
    for (int c = 0; c < 96; c++){
        ull xv = *(const ull*)(x + (size_t)c*HW);
        const float* wc = wc0 + c*8;
        #pragma unroll
        for (int r = 0; r < NRC; r++){
            float wv = wc[r];
            acc[r] = fma2(pack2(wv, wv), xv, acc[r]);
        }
    }
    ull* pr = part + lane*65 + wp*8;
    #pragma unroll
    for (int r = 0; r < NRC; r++) pr[r] = acc[r];
    __syncthreads();
    int r = threadIdx.x >> 5, pl = threadIdx.x & 31;
    ull s = part[pl*65 + r];
    #pragma unroll
    for (int ww = 1; ww < 8; ww++) s = add2(s, part[pl*65 + ww*8 + r]);
    float lo, hi; unpack2(s, lo, hi);
    float bb = bv[r]; lo += bb; hi += bb;
    float2 v; v.x = geluf(lo); v.y = geluf(hi);
    int po = (pg*32 + pl) << 1;
    *(float2*)(g_cpre + (size_t)b*NRC*HW + (size_t)r*HW + po) = v;

    if (blockIdx.x == 0){
        const float Ls[3] = {0.45f, 0.75f, 1.05f};
        const float Wv[3] = {0.14f, 0.2f, 0.28f};
        for (int i = threadIdx.x; i < NP*81; i += 256){
            int pp = i/81, idx = i%81, ky = idx/9, kx = idx%9;
            float yy = -1.0f + 0.25f*ky, xx = -1.0f + 0.25f*kx;
            float ca = c_ca[pp], sa = c_sa[pp];
            float L = Ls[pp%3], W = Wv[(pp/3)%3];
            float xr = xx*ca + yy*sa;
            float yr = -xx*sa + yy*ca;
            float xl = __fdividef(xr, L);
            float tt = 1.0f - fminf(fabsf(xl), 1.0f);
            float tp = tt*sqrtf(tt);
            float yrw = __fdividef(yr, W);
            float core = __expf(-0.5f*(xl*xl + yrw*yrw));
            ridgeS[i] = tp * core * fmaxf(1.0f - yrw*yrw, 0.0f);
        }
        __syncthreads();
        int wpp = threadIdx.x >> 5, ln = threadIdx.x & 31;
        float* rp = ridgeS + wpp*81;
        float su = 0.f;
        for (int j = ln; j < 81; j += 32) su += rp[j];
        #pragma unroll
        for (int o = 16; o > 0; o >>= 1) su += __shfl_xor_sync(0xffffffffu, su, o);
        float mean = su*(1.0f/81.0f);
        float a = 0.f;
        for (int j = ln; j < 81; j += 32) a += fabsf(rp[j]-mean);
        #pragma unroll
        for (int o = 16; o > 0; o >>= 1) a += __shfl_xor_sync(0xffffffffu, a, o);
        float den = fmaxf(a, 1e-6f);
        for (int j = ln; j < 81; j += 32)
            g_kern[wpp*81+j] = (rp[j]-mean)/den + 0.05f*pdelta[wpp*81+j];
    }
}

// ---------------- K23: conv3x3+gelu on halo-2 region, cm/dn, hp, cs, stats ----------------
__global__ __launch_bounds__(512) void k23_conv(const float* __restrict__ w,
                                                const float* __restrict__ bv){
    __shared__ float ws[576];
    __shared__ float bs[NRC];
    __shared__ float ts[NRC][22][22];
    __shared__ float cr[NRC][20][20];
    __shared__ float cms[20][20];
    __shared__ float hps[18][18];
    __shared__ float red[5][8];
    int tid = threadIdx.x;
    for (int i = tid; i < 576; i += 512) ws[i] = w[(i & 7)*72 + (i >> 3)];
    if (tid < NRC) bs[tid] = bv[tid];
    int blk = blockIdx.x; int b = blk >> 4, tile = blk & 15;
    int ty0 = (tile >> 2) << 4, tx0 = (tile & 3) << 4;
    const float* in = g_cpre + (size_t)b*NRC*HW;
    for (int i = tid; i < NRC*484; i += 512){
        int ic = i / 484, rem = i % 484, ly = rem / 22, lx = rem % 22;
        int gy = ty0 - 3 + ly, gx = tx0 - 3 + lx;
        float v = 0.f;
        if (gy >= 0 && gy < 64 && gx >= 0 && gx < 64) v = in[ic*HW + gy*64 + gx];
        ts[ic][ly][lx] = v;
    }
    __syncthreads();
    for (int i = tid; i < 1600; i += 512){
        int oc = i / 200, pi = i % 200;
        int py = pi / 10, px = (pi % 10) << 1;
        float bb = bs[oc];
        ull acc = pack2(bb, bb);
        #pragma unroll
        for (int ic = 0; ic < NRC; ic++){
            #pragma unroll
            for (int dy = 0; dy < 3; dy++){
                #pragma unroll
                for (int dx = 0; dx < 3; dx++){
                    float vlo = ts[ic][py+dy][px+dx];
                    float vhi = ts[ic][py+dy][px+dx+1];
                    float wv = ws[(ic*9 + dy*3 + dx)*8 + oc];
                    acc = fma2(pack2(wv, wv), pack2(vlo, vhi), acc);
                }
            }
        }
        float lo, hi; unpack2(acc, lo, hi);
        cr[oc][py][px]   = geluf(lo);
        cr[oc][py][px+1] = geluf(hi);
    }
    __syncthreads();
    for (int i = tid; i < 400; i += 512){
        int ly = i / 20, lx = i % 20;
        int gy = ty0 - 2 + ly, gx = tx0 - 2 + lx;
        float cmv = 0.f;
        if (gy >= 0 && gy < 64 && gx >= 0 && gx < 64){
            float m = 0.f;
            #pragma unroll
            for (int oc = 0; oc < NRC; oc++) m += cr[oc][ly][lx];
            cmv = m * 0.125f;
        }
        cms[ly][lx] = cmv;
        if (ly >= 2 && ly < 18 && lx >= 2 && lx < 18){
            float a = 0.f;
            #pragma unroll
            for (int oc = 0; oc < NRC; oc++) a += fabsf(cr[oc][ly][lx]);
            g_dn[b*HW + gy*64 + gx] = a * 0.125f;
        }
    }
    for (int i = tid; i < 1024; i += 512){
        int oc = i >> 7, pi = i & 127;
        int py = pi >> 3, px = (pi & 7) << 1;
        float2 v; v.x = cr[oc][py+2][px+2]; v.y = cr[oc][py+2][px+3];
        *(float2*)(g_car + (size_t)b*NRC*HW + (size_t)oc*HW + (ty0+py)*64 + tx0+px) = v;
    }
    __syncthreads();
    for (int i = tid; i < 324; i += 512){
        int ly = i/18, lx = i%18;
        int gy = ty0-1+ly, gx = tx0-1+lx;
        float v = 0.f;
        if (gy>=0 && gy<64 && gx>=0 && gx<64){
            float s = 0.f;
            #pragma unroll
            for (int dy = 0; dy < 3; dy++)
                #pragma unroll
                for (int dx = 0; dx < 3; dx++) s += cms[ly+dy][lx+dx];
            v = cms[ly+1][lx+1] - s*(1.0f/9.0f);
        }
        hps[ly][lx] = v;
    }
    __syncthreads();
    if (tid < 256){
        int ty = tid >> 4, tx = tid & 15;
        float s = 0.f;
        #pragma unroll
        for (int dy = 0; dy < 3; dy++)
            #pragma unroll
            for (int dx = 0; dx < 3; dx++) s += fabsf(hps[ty+dy][tx+dx]);
        float cs = s*(1.0f/9.0f);
        int gi = b*HW + (ty0+ty)*64 + (tx0+tx);
        g_hp[gi] = hps[ty+1][tx+1];
        g_cs[gi] = cs;
        float a = 0.f;
        #pragma unroll
        for (int oc = 0; oc < NRC; oc++) a += fabsf(cr[oc][ty+2][tx+2]);
        float d = a * 0.125f;
        float cmn = cs, cmx = cs, dmn = d, dmx = d, ds = d;
        #pragma unroll
        for (int o = 16; o > 0; o >>= 1){
            cmn = fminf(cmn, __shfl_xor_sync(0xffffffffu, cmn, o));
            cmx = fmaxf(cmx, __shfl_xor_sync(0xffffffffu, cmx, o));
            dmn = fminf(dmn, __shfl_xor_sync(0xffffffffu, dmn, o));
            dmx = fmaxf(dmx, __shfl_xor_sync(0xffffffffu, dmx, o));
            ds += __shfl_xor_sync(0xffffffffu, ds, o);
        }
        int wd = tid >> 5, lane = tid & 31;
        if (lane == 0){ red[0][wd]=cmn; red[1][wd]=cmx; red[2][wd]=dmn; red[3][wd]=dmx; red[4][wd]=ds; }
    }
    __syncthreads();
    if (tid == 0){
        float c0=red[0][0], c1=red[1][0], d0=red[2][0], d1=red[3][0], dsu=red[4][0];
        for (int j = 1; j < 8; j++){
            c0 = fminf(c0, red[0][j]); c1 = fmaxf(c1, red[1][j]);
            d0 = fminf(d0, red[2][j]); d1 = fmaxf(d1, red[3][j]);
            dsu += red[4][j];
        }
        float* pp = g_part + blk*8;
        pp[0]=c0; pp[1]=c1; pp[2]=d0; pp[3]=d1; pp[4]=dsu;
    }
}

// ---------------- K57: stats + gating + responses + final ss; 256 blocks of 16x8 ----------------
__global__ __launch_bounds__(256) void k57_main(const float* __restrict__ theta,
                                                const float* __restrict__ length,
                                                const float* __restrict__ width,
                                                const float* __restrict__ plog,
                                                const float* __restrict__ obj,
                                                const float* __restrict__ alpha,
                                                const float* __restrict__ curv){
    __shared__ float hps[18*26];
    __shared__ float kern[NP*81];
    __shared__ float m0s[20*28];
    __shared__ float g0s[12*20];
    __shared__ float ers[16*24];
    __shared__ float s0s[10*18];
    __shared__ float obs[10*18];
    __shared__ float cmin[16*28];
    __shared__ float cmax[8*24];
    __shared__ float gcol[8*20];
    __shared__ float st_s[5];
    int blk = blockIdx.x; int b = blk >> 5, tile = blk & 31;
    int ty0 = (tile >> 2) << 3, tx0 = (tile & 3) << 4;
    int tid = threadIdx.x;

    const float* hp = g_hp + b*HW;
    for (int i = tid; i < 468; i += 256){
        int ly = i/26, lx = i%26;
        int gy = ty0-5+ly, gx = tx0-5+lx;
        hps[i] = (gy>=0 && gy<64 && gx>=0 && gx<64) ? hp[gy*64+gx] : 0.f;
    }
    for (int i = tid; i < NP*81; i += 256) kern[i] = g_kern[i];
    if (tid < 32){
        int lane = tid;
        float v0=1e30f, v1=-1e30f, v2=1e30f, v3=-1e30f, v4=0.f;
        if (lane < 16){
            const float* pp = g_part + (b*16+lane)*8;
            v0=pp[0]; v1=pp[1]; v2=pp[2]; v3=pp[3]; v4=pp[4];
        }
        #pragma unroll
        for (int o = 8; o > 0; o >>= 1){
            v0 = fminf(v0, __shfl_down_sync(0xffffffffu, v0, o));
            v1 = fmaxf(v1, __shfl_down_sync(0xffffffffu, v1, o));
            v2 = fminf(v2, __shfl_down_sync(0xffffffffu, v2, o));
            v3 = fmaxf(v3, __shfl_down_sync(0xffffffffu, v3, o));
            v4 +=           __shfl_down_sync(0xffffffffu, v4, o);
        }
        if (lane == 0){
            st_s[0]=v0; st_s[1]=v1; st_s[2]=v2; st_s[3]=v3; st_s[4]=v4*(1.0f/4096.0f);
        }
    }
    __syncthreads();

    float csmn = st_s[0], csmx = st_s[1], dmn = st_s[2], dmx = st_s[3];
    float m = fmaxf(st_s[4], 1e-6f);
    float csden = fmaxf(csmx - csmn, 1e-6f);
    float ddmn = dmn/m, ddmx = dmx/m;
    float dsden = fmaxf(ddmx - ddmn, 1e-6f);
    const float* csb = g_cs + b*HW; const float* dnb = g_dn + b*HW;
    for (int i = tid; i < 560; i += 256){
        int ly = i/28, lx = i%28;
        int gy = ty0-6+ly, gx = tx0-6+lx;
        float mv = 1.0f, gv = 0.0f;
        if (gy>=0 && gy<64 && gx>=0 && gx<64){
            int gi = gy*64+gx;
            float csn = (csb[gi]-csmn)/csden;
            float dsn = (dnb[gi]/m - ddmn)/dsden;
            float ev = 0.65f*csn + 0.35f*dsn;
            mv = (ev >= 0.2f) ? 1.0f : 0.0f;
            gv = sigmf_((ev - 0.2f)*12.5f);
        }
        m0s[i] = mv;
        if (ly >= 4 && ly < 16 && lx >= 4 && lx < 24)
            g0s[(ly-4)*20 + (lx-4)] = gv;
    }
    __syncthreads();
    for (int i = tid; i < 448; i += 256){
        int ly = i/28, lx = i%28;
        float e = m0s[ly*28+lx];
        #pragma unroll
        for (int dy = 1; dy < 5; dy++) e = fminf(e, m0s[(ly+dy)*28+lx]);
        cmin[i] = e;
    }
    __syncthreads();
    for (int i = tid; i < 384; i += 256){
        int ly = i/24, lx = i%24;
        int gy = ty0-4+ly, gx = tx0-4+lx;
        float e = 0.f;
        if (gy>=0 && gy<64 && gx>=0 && gx<64){
            e = cmin[ly*28+lx];
            #pragma unroll
            for (int dx = 1; dx < 5; dx++) e = fminf(e, cmin[ly*28+lx+dx]);
        }
        ers[i] = e;
    }
    const float* ob = obj + b*HW;
    const float Ls[3] = {0.45f, 0.75f, 1.05f};
    const float Wv[3] = {0.14f, 0.2f, 0.28f};
    for (int i = tid; i < 180; i += 256){
        int ly = i/18, lx = i%18;
        int gy = ty0-1+ly, gx = tx0-1+lx;
        float sv = 0.f, ov = 0.f;
        if (gy>=0 && gy<64 && gx>=0 && gx<64){
            int gi = gy*64+gx; int t = b*HW + gi;
            ov = sigmf_(ob[gi]);
            float bias[NP];
            float ta = tanhf(theta[t]) * 3.14159265358979323846f;
            float cta, sta; __sincosf(ta, &sta, &cta);
            float lv = sigmf_(length[t])*0.85f + 0.25f;
            float wv = sigmf_(width[t])*0.22f + 0.08f;
            #pragma unroll
            for (int p = 0; p < NP; p++){
                float la = Ls[p%3], wa = Wv[(p/3)%3];
                float dl = lv - la, dw = wv - wa;
                bias[p] = plog[(size_t)b*NP*HW + p*HW + gi]
                        + 1.25f*(cta*c_ca[p] + sta*c_sa[p])
                        - dl*dl*12.5f
                        - dw*dw*100.0f;
            }
            int i1 = 0; float m1 = bias[0];
            #pragma unroll
            for (int p = 1; p < NP; p++) if (bias[p] > m1){ m1 = bias[p]; i1 = p; }
            int i2 = (i1 == 0) ? 1 : 0; float m2 = -1e30f;
            #pragma unroll
            for (int p = 0; p < NP; p++) if (p != i1 && bias[p] > m2){ m2 = bias[p]; i2 = p; }
            float e2 = __expf(m2 - m1);
            float inv = 1.0f/(1.0f + e2);
            float pw1 = inv, pw2 = e2*inv;
            const float* k1p = kern + i1*81;
            const float* k2p = kern + i2*81;
            float r1 = 0.f, r2v = 0.f;
            #pragma unroll
            for (int ky = 0; ky < 9; ky++){
                #pragma unroll
                for (int kx = 0; kx < 9; kx++){
                    float v = hps[(ly+ky)*26 + (lx+kx)];
                    r1  = fmaf(k1p[ky*9+kx], v, r1);
                    r2v = fmaf(k2p[ky*9+kx], v, r2v);
                }
            }
            sv = pw1*r1 + pw2*r2v;
        }
        s0s[i] = sv;
        obs[i] = ov;
    }
    __syncthreads();
    for (int i = tid; i < 352; i += 256){
        if (i < 192){
            int ty = i/24, lx = i%24;
            float e = ers[ty*24+lx];
            #pragma unroll
            for (int dy = 1; dy < 9; dy++) e = fmaxf(e, ers[(ty+dy)*24+lx]);
            cmax[i] = e;
        } else {
            int j = i - 192;
            int ty = j/20, lx = j%20;
            float g = g0s[ty*20+lx];
            #pragma unroll
            for (int dy = 1; dy < 5; dy++) g = fmaxf(g, g0s[(ty+dy)*20+lx]);
            gcol[j] = g;
        }
    }
    __syncthreads();
    if (tid < 128){
        int ty = tid >> 4, tx = tid & 15;
        float mask = cmax[ty*24+tx];
        #pragma unroll
        for (int dx = 1; dx < 9; dx++) mask = fmaxf(mask, cmax[ty*24+tx+dx]);
        float gate = gcol[ty*20+tx];
        #pragma unroll
        for (int dx = 1; dx < 5; dx++) gate = fmaxf(gate, gcol[ty*20+tx+dx]);
        float blob = 0.f, ssum = 0.f;
        #pragma unroll
        for (int dy = 0; dy < 3; dy++)
            #pragma unroll
            for (int dx = 0; dx < 3; dx++){
                blob += obs[(ty+dy)*18 + (tx+dx)];
                ssum += s0s[(ty+dy)*18 + (tx+dx)];
            }
        blob *= (1.0f/9.0f);
        float ss1 = s0s[(ty+1)*18 + (tx+1)] - ssum*(1.0f/9.0f);
        int t = b*HW + (ty0+ty)*64 + (tx0+tx);
        float gatef = gate * mask;
        float dmean = fmaxf(st_s[4], 1e-6f);
        float dens = g_dn[t] / dmean;
        float sg = sigmf_(alpha[t]) * (blob * gatef) * (0.7f + 0.3f*fminf(fmaxf(dens, 0.f), 2.f));
        g_sf[t] = sg * ss1 * (1.0f + 0.15f*tanhf(curv[t]));
    }
}

// ---------------- K8: feats -> 8 (gelu) -> 768; fc-quarter per block, 4 warps x 48 fc, 4 px/thread ----------------
__global__ __launch_bounds__(128) void k8_out(const float* __restrict__ theta,
                                              const float* __restrict__ curv,
                                              const float* __restrict__ w1,
                                              const float* __restrict__ b1,
                                              const float* __restrict__ w2,
                                              const float* __restrict__ b2,
                                              float* __restrict__ out){
    extern __shared__ ull sh[];
    ull*   w2p = sh;                     // 1536 packed (w,w) — this block's fc quarter
    float* b2s = (float*)(sh + 1536);    // 192
    ull*   w1p = (ull*)(b2s + 192);      // 96
    float* b1s = (float*)(w1p + 96);     // 8
    int blk = blockIdx.x;                // 1024 blocks = 256 pixel-groups x 4 fc quarters
    int qsel = blk & 3, pgall = blk >> 2;
    int b = pgall >> 5, pgi = pgall & 31;
    const float* w2q = w2 + (size_t)qsel*192*8;
    for (int i = threadIdx.x; i < 1536; i += 128){ float v = w2q[i]; w2p[i] = pack2(v, v); }
    for (int i = threadIdx.x; i < 192; i += 128) b2s[i] = b2[qsel*192 + i];
    for (int i = threadIdx.x; i < 96; i += 128){ float v = w1[i]; w1p[i] = pack2(v, v); }
    if (threadIdx.x < 8) b1s[threadIdx.x] = b1[threadIdx.x];
    __syncthreads();

    int wp = threadIdx.x >> 5, lane = threadIdx.x & 31;
    int p = (pgi*32 + lane) << 2;        // pixel quad
    int base = b*HW + p;
    float4 ss = *(const float4*)(g_sf + base);
    float4 th = *(const float4*)(theta + base);
    float4 cv = *(const float4*)(curv + base);
    ull fl[12], fh[12];
    const float* car = g_car + (size_t)b*NRC*HW + p;
    #pragma unroll
    for (int r = 0; r < NRC; r++){
        float4 c = *(const float4*)(car + (size_t)r*HW);
        fl[r] = pack2(c.x*ss.x, c.y*ss.y);
        fh[r] = pack2(c.z*ss.z, c.w*ss.w);
    }
    fl[8] = pack2(ss.x, ss.y);
    fh[8] = pack2(ss.z, ss.w);
    const float PIF = 3.14159265358979323846f;
    float a0 = tanhf(th.x)*PIF, a1 = tanhf(th.y)*PIF, a2 = tanhf(th.z)*PIF, a3 = tanhf(th.w)*PIF;
    fl[9]  = pack2(cosf(a0)*ss.x, cosf(a1)*ss.y);
    fh[9]  = pack2(cosf(a2)*ss.z, cosf(a3)*ss.w);
    fl[10] = pack2(sinf(a0)*ss.x, sinf(a1)*ss.y);
    fh[10] = pack2(sinf(a2)*ss.z, sinf(a3)*ss.w);
    fl[11] = pack2(tanhf(cv.x)*ss.x, tanhf(cv.y)*ss.y);
    fh[11] = pack2(tanhf(cv.z)*ss.z, tanhf(cv.w)*ss.w);

    ull hl[NRC], hh[NRC];
    #pragma unroll
    for (int r = 0; r < NRC; r++){
        ull accl = pack2(b1s[r], b1s[r]);
        ull acch = accl;
        #pragma unroll
        for (int j = 0; j < 12; j++){
            ull wv = w1p[r*12+j];
            accl = fma2(wv, fl[j], accl);
            acch = fma2(wv, fh[j], acch);
        }
        float lo, hi; unpack2(accl, lo, hi);
        hl[r] = pack2(geluf(lo), geluf(hi));
        unpack2(acch, lo, hi);
        hh[r] = pack2(geluf(lo), geluf(hi));
    }
    float* o = out + (size_t)b*NFC*HW + (size_t)(qsel*192)*HW + p;
    int fc0 = wp * 48;
    #pragma unroll 2
    for (int j = 0; j < 48; j++){
        int fc = fc0 + j;                // local within quarter
        float bb = b2s[fc];
        ull accl = pack2(bb, bb);
        ull acch = accl;
        const ulonglong2* wr = (const ulonglong2*)(w2p + fc*8);
        #pragma unroll
        for (int q = 0; q < 4; q++){
            ulonglong2 wv = wr[q];
            accl = fma2(wv.x, hl[q*2],   accl);
            acch = fma2(wv.x, hh[q*2],   acch);
            accl = fma2(wv.y, hl[q*2+1], accl);
            acch = fma2(wv.y, hh[q*2+1], acch);
        }
        float4 v;
        unpack2(accl, v.x, v.y);
        unpack2(acch, v.z, v.w);
        *(float4*)(o + (size_t)fc*HW) = v;
    }
}

// ---------------- host ----------------
extern "C" void kernel_launch(void* const* d_in, const int* in_sizes, int n_in,
                              void* d_out, int out_size){
    const float* fm    = (const float*)d_in[0];
    const float* theta = (const float*)d_in[1];
    const float* len   = (const float*)d_in[2];
    const float* wid   = (const float*)d_in[3];
    const float* curv  = (const float*)d_in[4];
    const float* alpha = (const float*)d_in[5];
    const float* obj   = (const float*)d_in[6];
    const float* plog  = (const float*)d_in[7];
    const float* fp1w  = (const float*)d_in[8];
    const float* fp1b  = (const float*)d_in[9];
    const float* fp2w  = (const float*)d_in[10];
    const float* fp2b  = (const float*)d_in[11];
    const float* pm1w  = (const float*)d_in[12];
    const float* pm1b  = (const float*)d_in[13];
    const float* pm2w  = (const float*)d_in[14];
    const float* pm2b  = (const float*)d_in[15];
    const float* pdel  = (const float*)d_in[16];

    cudaFuncSetAttribute(k1_gemm, cudaFuncAttributeMaxDynamicSharedMemorySize, 41216);
    cudaFuncSetAttribute(k8_out,  cudaFuncAttributeMaxDynamicSharedMemorySize, 14112);

    k1_gemm<<<512,256,41216>>>(fm, fp1w, fp1b, pdel);
    k23_conv<<<128,512>>>(fp2w, fp2b);
    k57_main<<<256,256>>>(theta, len, wid, plog, obj, alpha, curv);
    k8_out<<<1024,128,14112>>>(theta, curv, pm1w, pm1b, pm2w, pm2b, (float*)d_out);
}

// round 17
// speedup vs baseline: 1.0727x; 1.0727x over previous
#include <cuda_runtime.h>
#include <math.h>

#define HW   4096
#define NB   8
#define NFC  768
#define NRC  8
#define NP   8

typedef unsigned long long ull;

// ---------------- scratch ----------------
__device__ float g_cpre[NB*NRC*HW];
__device__ float g_car [NB*NRC*HW];
__device__ float g_dn  [NB*HW];
__device__ float g_hp  [NB*HW];
__device__ float g_cs  [NB*HW];
__device__ float g_h   [NB*NRC*HW];   // hidden layer (post-gelu) per pixel
__device__ float g_part[128*8];
__device__ float g_kern[NP*81];

// ---------------- helpers ----------------
__device__ __forceinline__ ull pack2(float lo, float hi){ ull r; asm("mov.b64 %0,{%1,%2};":"=l"(r):"f"(lo),"f"(hi)); return r; }
__device__ __forceinline__ ull fma2(ull a, ull b, ull c){ ull d; asm("fma.rn.f32x2 %0,%1,%2,%3;":"=l"(d):"l"(a),"l"(b),"l"(c)); return d; }
__device__ __forceinline__ ull add2(ull a, ull b){ ull d; asm("add.rn.f32x2 %0,%1,%2;":"=l"(d):"l"(a),"l"(b)); return d; }
__device__ __forceinline__ void unpack2(ull v, float&lo, float&hi){ asm("mov.b64 {%0,%1},%2;":"=f"(lo),"=f"(hi):"l"(v)); }
__device__ __forceinline__ float geluf(float x){ return 0.5f*x*(1.0f+erff(x*0.70710678118654752f)); }
__device__ __forceinline__ float sigmf_(float x){ return 1.0f/(1.0f+__expf(-x)); }

__device__ __constant__ float c_ca[8] = {1.0f, 0.707106781f, 6.12323426e-17f, -0.707106781f,
                                         -1.0f, -0.707106781f, -1.83697015e-16f, 0.707106781f};
__device__ __constant__ float c_sa[8] = {0.0f, 0.707106781f, 1.0f, 0.707106781f,
                                         1.22464685e-16f, -0.707106781f, -1.0f, -0.707106781f};

// ---------------- K1: 768->8 1x1 conv + gelu; warp-granular 8-way K-split (2 px/thread) ----------------
__global__ __launch_bounds__(256) void k1_gemm(const float* __restrict__ fm,
                                               const float* __restrict__ w,
                                               const float* __restrict__ bv,
                                               const float* __restrict__ pdelta){
    extern __shared__ char dsmc[];
    float* wsf = (float*)dsmc;                 // 6144 floats, c-major [c][r]
    ull*   part = (ull*)(dsmc + 24576);        // 32*65 ull
    __shared__ float ridgeS[NP*81];
    for (int i = threadIdx.x; i < NFC*NRC; i += 256){
        int c = i >> 3, r = i & 7;
        wsf[i] = w[r*NFC + c];
    }
    __syncthreads();
    int blk = blockIdx.x;                      // 512 blocks
    int b = blk >> 6, pg = blk & 63;
    int wp = threadIdx.x >> 5, lane = threadIdx.x & 31;
    int p = (pg*32 + lane) << 1;
    const float* x = fm + (size_t)b*NFC*HW + (size_t)(wp*96)*HW + p;
    const float* wc0 = wsf + wp*96*8;
    ull acc[NRC];
    #pragma unroll
    for (int r = 0; r < NRC; r++) acc[r] = 0ull;
    #pragma unroll 8
    for (int c = 0; c < 96; c++){
        ull xv = *(const ull*)(x + (size_t)c*HW);
        const float* wc = wc0 + c*8;
        #pragma unroll
        for (int r = 0; r < NRC; r++){
            float wv = wc[r];
            acc[r] = fma2(pack2(wv, wv), xv, acc[r]);
        }
    }
    ull* pr = part + lane*65 + wp*8;
    #pragma unroll
    for (int r = 0; r < NRC; r++) pr[r] = acc[r];
    __syncthreads();
    int r = threadIdx.x >> 5, pl = threadIdx.x & 31;
    ull s = part[pl*65 + r];
    #pragma unroll
    for (int ww = 1; ww < 8; ww++) s = add2(s, part[pl*65 + ww*8 + r]);
    float lo, hi; unpack2(s, lo, hi);
    float bb = bv[r]; lo += bb; hi += bb;
    float2 v; v.x = geluf(lo); v.y = geluf(hi);
    int po = (pg*32 + pl) << 1;
    *(float2*)(g_cpre + (size_t)b*NRC*HW + (size_t)r*HW + po) = v;

    if (blockIdx.x == 0){
        const float Ls[3] = {0.45f, 0.75f, 1.05f};
        const float Wv[3] = {0.14f, 0.2f, 0.28f};
        for (int i = threadIdx.x; i < NP*81; i += 256){
            int pp = i/81, idx = i%81, ky = idx/9, kx = idx%9;
            float yy = -1.0f + 0.25f*ky, xx = -1.0f + 0.25f*kx;
            float ca = c_ca[pp], sa = c_sa[pp];
            float L = Ls[pp%3], W = Wv[(pp/3)%3];
            float xr = xx*ca + yy*sa;
            float yr = -xx*sa + yy*ca;
            float xl = __fdividef(xr, L);
            float tt = 1.0f - fminf(fabsf(xl), 1.0f);
            float tp = tt*sqrtf(tt);
            float yrw = __fdividef(yr, W);
            float core = __expf(-0.5f*(xl*xl + yrw*yrw));
            ridgeS[i] = tp * core * fmaxf(1.0f - yrw*yrw, 0.0f);
        }
        __syncthreads();
        int wpp = threadIdx.x >> 5, ln = threadIdx.x & 31;
        float* rp = ridgeS + wpp*81;
        float su = 0.f;
        for (int j = ln; j < 81; j += 32) su += rp[j];
        #pragma unroll
        for (int o = 16; o > 0; o >>= 1) su += __shfl_xor_sync(0xffffffffu, su, o);
        float mean = su*(1.0f/81.0f);
        float a = 0.f;
        for (int j = ln; j < 81; j += 32) a += fabsf(rp[j]-mean);
        #pragma unroll
        for (int o = 16; o > 0; o >>= 1) a += __shfl_xor_sync(0xffffffffu, a, o);
        float den = fmaxf(a, 1e-6f);
        for (int j = ln; j < 81; j += 32)
            g_kern[wpp*81+j] = (rp[j]-mean)/den + 0.05f*pdelta[wpp*81+j];
    }
}

// ---------------- K23: conv3x3+gelu on halo-2 region, cm/dn, hp, cs, stats ----------------
__global__ __launch_bounds__(512) void k23_conv(const float* __restrict__ w,
                                                const float* __restrict__ bv){
    __shared__ float ws[576];
    __shared__ float bs[NRC];
    __shared__ float ts[NRC][22][22];
    __shared__ float cr[NRC][20][20];
    __shared__ float cms[20][20];
    __shared__ float hps[18][18];
    __shared__ float red[5][8];
    int tid = threadIdx.x;
    for (int i = tid; i < 576; i += 512) ws[i] = w[(i & 7)*72 + (i >> 3)];
    if (tid < NRC) bs[tid] = bv[tid];
    int blk = blockIdx.x; int b = blk >> 4, tile = blk & 15;
    int ty0 = (tile >> 2) << 4, tx0 = (tile & 3) << 4;
    const float* in = g_cpre + (size_t)b*NRC*HW;
    for (int i = tid; i < NRC*484; i += 512){
        int ic = i / 484, rem = i % 484, ly = rem / 22, lx = rem % 22;
        int gy = ty0 - 3 + ly, gx = tx0 - 3 + lx;
        float v = 0.f;
        if (gy >= 0 && gy < 64 && gx >= 0 && gx < 64) v = in[ic*HW + gy*64 + gx];
        ts[ic][ly][lx] = v;
    }
    __syncthreads();
    for (int i = tid; i < 1600; i += 512){
        int oc = i / 200, pi = i % 200;
        int py = pi / 10, px = (pi % 10) << 1;
        float bb = bs[oc];
        ull acc = pack2(bb, bb);
        #pragma unroll
        for (int ic = 0; ic < NRC; ic++){
            #pragma unroll
            for (int dy = 0; dy < 3; dy++){
                #pragma unroll
                for (int dx = 0; dx < 3; dx++){
                    float vlo = ts[ic][py+dy][px+dx];
                    float vhi = ts[ic][py+dy][px+dx+1];
                    float wv = ws[(ic*9 + dy*3 + dx)*8 + oc];
                    acc = fma2(pack2(wv, wv), pack2(vlo, vhi), acc);
                }
            }
        }
        float lo, hi; unpack2(acc, lo, hi);
        cr[oc][py][px]   = geluf(lo);
        cr[oc][py][px+1] = geluf(hi);
    }
    __syncthreads();
    for (int i = tid; i < 400; i += 512){
        int ly = i / 20, lx = i % 20;
        int gy = ty0 - 2 + ly, gx = tx0 - 2 + lx;
        float cmv = 0.f;
        if (gy >= 0 && gy < 64 && gx >= 0 && gx < 64){
            float m = 0.f;
            #pragma unroll
            for (int oc = 0; oc < NRC; oc++) m += cr[oc][ly][lx];
            cmv = m * 0.125f;
        }
        cms[ly][lx] = cmv;
        if (ly >= 2 && ly < 18 && lx >= 2 && lx < 18){
            float a = 0.f;
            #pragma unroll
            for (int oc = 0; oc < NRC; oc++) a += fabsf(cr[oc][ly][lx]);
            g_dn[b*HW + gy*64 + gx] = a * 0.125f;
        }
    }
    for (int i = tid; i < 1024; i += 512){
        int oc = i >> 7, pi = i & 127;
        int py = pi >> 3, px = (pi & 7) << 1;
        float2 v; v.x = cr[oc][py+2][px+2]; v.y = cr[oc][py+2][px+3];
        *(float2*)(g_car + (size_t)b*NRC*HW + (size_t)oc*HW + (ty0+py)*64 + tx0+px) = v;
    }
    __syncthreads();
    for (int i = tid; i < 324; i += 512){
        int ly = i/18, lx = i%18;
        int gy = ty0-1+ly, gx = tx0-1+lx;
        float v = 0.f;
        if (gy>=0 && gy<64 && gx>=0 && gx<64){
            float s = 0.f;
            #pragma unroll
            for (int dy = 0; dy < 3; dy++)
                #pragma unroll
                for (int dx = 0; dx < 3; dx++) s += cms[ly+dy][lx+dx];
            v = cms[ly+1][lx+1] - s*(1.0f/9.0f);
        }
        hps[ly][lx] = v;
    }
    __syncthreads();
    if (tid < 256){
        int ty = tid >> 4, tx = tid & 15;
        float s = 0.f;
        #pragma unroll
        for (int dy = 0; dy < 3; dy++)
            #pragma unroll
            for (int dx = 0; dx < 3; dx++) s += fabsf(hps[ty+dy][tx+dx]);
        float cs = s*(1.0f/9.0f);
        int gi = b*HW + (ty0+ty)*64 + (tx0+tx);
        g_hp[gi] = hps[ty+1][tx+1];
        g_cs[gi] = cs;
        float a = 0.f;
        #pragma unroll
        for (int oc = 0; oc < NRC; oc++) a += fabsf(cr[oc][ty+2][tx+2]);
        float d = a * 0.125f;
        float cmn = cs, cmx = cs, dmn = d, dmx = d, ds = d;
        #pragma unroll
        for (int o = 16; o > 0; o >>= 1){
            cmn = fminf(cmn, __shfl_xor_sync(0xffffffffu, cmn, o));
            cmx = fmaxf(cmx, __shfl_xor_sync(0xffffffffu, cmx, o));
            dmn = fminf(dmn, __shfl_xor_sync(0xffffffffu, dmn, o));
            dmx = fmaxf(dmx, __shfl_xor_sync(0xffffffffu, dmx, o));
            ds += __shfl_xor_sync(0xffffffffu, ds, o);
        }
        int wd = tid >> 5, lane = tid & 31;
        if (lane == 0){ red[0][wd]=cmn; red[1][wd]=cmx; red[2][wd]=dmn; red[3][wd]=dmx; red[4][wd]=ds; }
    }
    __syncthreads();
    if (tid == 0){
        float c0=red[0][0], c1=red[1][0], d0=red[2][0], d1=red[3][0], dsu=red[4][0];
        for (int j = 1; j < 8; j++){
            c0 = fminf(c0, red[0][j]); c1 = fmaxf(c1, red[1][j]);
            d0 = fminf(d0, red[2][j]); d1 = fmaxf(d1, red[3][j]);
            dsu += red[4][j];
        }
        float* pp = g_part + blk*8;
        pp[0]=c0; pp[1]=c1; pp[2]=d0; pp[3]=d1; pp[4]=dsu;
    }
}

// ---------------- K57: stats + gating + responses + final ss + hidden layer h ----------------
__global__ __launch_bounds__(256) void k57_main(const float* __restrict__ theta,
                                                const float* __restrict__ length,
                                                const float* __restrict__ width,
                                                const float* __restrict__ plog,
                                                const float* __restrict__ obj,
                                                const float* __restrict__ alpha,
                                                const float* __restrict__ curv,
                                                const float* __restrict__ w1,
                                                const float* __restrict__ b1){
    __shared__ float hps[18*26];
    __shared__ float kern[NP*81];
    __shared__ float m0s[20*28];
    __shared__ float g0s[12*20];
    __shared__ float ers[16*24];
    __shared__ float s0s[10*18];
    __shared__ float obs[10*18];
    __shared__ float cmin[16*28];
    __shared__ float cmax[8*24];
    __shared__ float gcol[8*20];
    __shared__ float st_s[5];
    __shared__ float w1s[96];
    __shared__ float b1s[8];
    int blk = blockIdx.x; int b = blk >> 5, tile = blk & 31;
    int ty0 = (tile >> 2) << 3, tx0 = (tile & 3) << 4;
    int tid = threadIdx.x;

    const float* hp = g_hp + b*HW;
    for (int i = tid; i < 468; i += 256){
        int ly = i/26, lx = i%26;
        int gy = ty0-5+ly, gx = tx0-5+lx;
        hps[i] = (gy>=0 && gy<64 && gx>=0 && gx<64) ? hp[gy*64+gx] : 0.f;
    }
    for (int i = tid; i < NP*81; i += 256) kern[i] = g_kern[i];
    if (tid >= 128 && tid < 224) w1s[tid-128] = w1[tid-128];
    if (tid >= 224 && tid < 232) b1s[tid-224] = b1[tid-224];
    if (tid < 32){
        int lane = tid;
        float v0=1e30f, v1=-1e30f, v2=1e30f, v3=-1e30f, v4=0.f;
        if (lane < 16){
            const float* pp = g_part + (b*16+lane)*8;
            v0=pp[0]; v1=pp[1]; v2=pp[2]; v3=pp[3]; v4=pp[4];
        }
        #pragma unroll
        for (int o = 8; o > 0; o >>= 1){
            v0 = fminf(v0, __shfl_down_sync(0xffffffffu, v0, o));
            v1 = fmaxf(v1, __shfl_down_sync(0xffffffffu, v1, o));
            v2 = fminf(v2, __shfl_down_sync(0xffffffffu, v2, o));
            v3 = fmaxf(v3, __shfl_down_sync(0xffffffffu, v3, o));
            v4 +=           __shfl_down_sync(0xffffffffu, v4, o);
        }
        if (lane == 0){
            st_s[0]=v0; st_s[1]=v1; st_s[2]=v2; st_s[3]=v3; st_s[4]=v4*(1.0f/4096.0f);
        }
    }
    __syncthreads();

    float csmn = st_s[0], csmx = st_s[1], dmn = st_s[2], dmx = st_s[3];
    float m = fmaxf(st_s[4], 1e-6f);
    float csden = fmaxf(csmx - csmn, 1e-6f);
    float ddmn = dmn/m, ddmx = dmx/m;
    float dsden = fmaxf(ddmx - ddmn, 1e-6f);
    const float* csb = g_cs + b*HW; const float* dnb = g_dn + b*HW;
    for (int i = tid; i < 560; i += 256){
        int ly = i/28, lx = i%28;
        int gy = ty0-6+ly, gx = tx0-6+lx;
        float mv = 1.0f, gv = 0.0f;
        if (gy>=0 && gy<64 && gx>=0 && gx<64){
            int gi = gy*64+gx;
            float csn = (csb[gi]-csmn)/csden;
            float dsn = (dnb[gi]/m - ddmn)/dsden;
            float ev = 0.65f*csn + 0.35f*dsn;
            mv = (ev >= 0.2f) ? 1.0f : 0.0f;
            gv = sigmf_((ev - 0.2f)*12.5f);
        }
        m0s[i] = mv;
        if (ly >= 4 && ly < 16 && lx >= 4 && lx < 24)
            g0s[(ly-4)*20 + (lx-4)] = gv;
    }
    __syncthreads();
    for (int i = tid; i < 448; i += 256){
        int ly = i/28, lx = i%28;
        float e = m0s[ly*28+lx];
        #pragma unroll
        for (int dy = 1; dy < 5; dy++) e = fminf(e, m0s[(ly+dy)*28+lx]);
        cmin[i] = e;
    }
    __syncthreads();
    for (int i = tid; i < 384; i += 256){
        int ly = i/24, lx = i%24;
        int gy = ty0-4+ly, gx = tx0-4+lx;
        float e = 0.f;
        if (gy>=0 && gy<64 && gx>=0 && gx<64){
            e = cmin[ly*28+lx];
            #pragma unroll
            for (int dx = 1; dx < 5; dx++) e = fminf(e, cmin[ly*28+lx+dx]);
        }
        ers[i] = e;
    }
    const float* ob = obj + b*HW;
    const float Ls[3] = {0.45f, 0.75f, 1.05f};
    const float Wv[3] = {0.14f, 0.2f, 0.28f};
    for (int i = tid; i < 180; i += 256){
        int ly = i/18, lx = i%18;
        int gy = ty0-1+ly, gx = tx0-1+lx;
        float sv = 0.f, ov = 0.f;
        if (gy>=0 && gy<64 && gx>=0 && gx<64){
            int gi = gy*64+gx; int t = b*HW + gi;
            ov = sigmf_(ob[gi]);
            float bias[NP];
            float ta = tanhf(theta[t]) * 3.14159265358979323846f;
            float cta, sta; __sincosf(ta, &sta, &cta);
            float lv = sigmf_(length[t])*0.85f + 0.25f;
            float wv = sigmf_(width[t])*0.22f + 0.08f;
            #pragma unroll
            for (int p = 0; p < NP; p++){
                float la = Ls[p%3], wa = Wv[(p/3)%3];
                float dl = lv - la, dw = wv - wa;
                bias[p] = plog[(size_t)b*NP*HW + p*HW + gi]
                        + 1.25f*(cta*c_ca[p] + sta*c_sa[p])
                        - dl*dl*12.5f
                        - dw*dw*100.0f;
            }
            int i1 = 0; float m1 = bias[0];
            #pragma unroll
            for (int p = 1; p < NP; p++) if (bias[p] > m1){ m1 = bias[p]; i1 = p; }
            int i2 = (i1 == 0) ? 1 : 0; float m2 = -1e30f;
            #pragma unroll
            for (int p = 0; p < NP; p++) if (p != i1 && bias[p] > m2){ m2 = bias[p]; i2 = p; }
            float e2 = __expf(m2 - m1);
            float inv = 1.0f/(1.0f + e2);
            float pw1 = inv, pw2 = e2*inv;
            const float* k1p = kern + i1*81;
            const float* k2p = kern + i2*81;
            float r1 = 0.f, r2v = 0.f;
            #pragma unroll
            for (int ky = 0; ky < 9; ky++){
                #pragma unroll
                for (int kx = 0; kx < 9; kx++){
                    float v = hps[(ly+ky)*26 + (lx+kx)];
                    r1  = fmaf(k1p[ky*9+kx], v, r1);
                    r2v = fmaf(k2p[ky*9+kx], v, r2v);
                }
            }
            sv = pw1*r1 + pw2*r2v;
        }
        s0s[i] = sv;
        obs[i] = ov;
    }
    __syncthreads();
    for (int i = tid; i < 352; i += 256){
        if (i < 192){
            int ty = i/24, lx = i%24;
            float e = ers[ty*24+lx];
            #pragma unroll
            for (int dy = 1; dy < 9; dy++) e = fmaxf(e, ers[(ty+dy)*24+lx]);
            cmax[i] = e;
        } else {
            int j = i - 192;
            int ty = j/20, lx = j%20;
            float g = g0s[ty*20+lx];
            #pragma unroll
            for (int dy = 1; dy < 5; dy++) g = fmaxf(g, g0s[(ty+dy)*20+lx]);
            gcol[j] = g;
        }
    }
    __syncthreads();
    if (tid < 128){
        int ty = tid >> 4, tx = tid & 15;
        float mask = cmax[ty*24+tx];
        #pragma unroll
        for (int dx = 1; dx < 9; dx++) mask = fmaxf(mask, cmax[ty*24+tx+dx]);
        float gate = gcol[ty*20+tx];
        #pragma unroll
        for (int dx = 1; dx < 5; dx++) gate = fmaxf(gate, gcol[ty*20+tx+dx]);
        float blob = 0.f, ssum = 0.f;
        #pragma unroll
        for (int dy = 0; dy < 3; dy++)
            #pragma unroll
            for (int dx = 0; dx < 3; dx++){
                blob += obs[(ty+dy)*18 + (tx+dx)];
                ssum += s0s[(ty+dy)*18 + (tx+dx)];
            }
        blob *= (1.0f/9.0f);
        float ss1 = s0s[(ty+1)*18 + (tx+1)] - ssum*(1.0f/9.0f);
        int pix = (ty0+ty)*64 + (tx0+tx);
        int t = b*HW + pix;
        float gatef = gate * mask;
        float dmean = fmaxf(st_s[4], 1e-6f);
        float dens = g_dn[t] / dmean;
        float sg = sigmf_(alpha[t]) * (blob * gatef) * (0.7f + 0.3f*fminf(fmaxf(dens, 0.f), 2.f));
        float ss = sg * ss1 * (1.0f + 0.15f*tanhf(curv[t]));

        // ---- hidden layer h = gelu(W1 @ f + b1), f = [car*ss, ss, dx*ss, dy*ss, cv*ss] ----
        float ta = tanhf(theta[t]) * 3.14159265358979323846f;
        float sta, cta; __sincosf(ta, &sta, &cta);
        float cvt = tanhf(curv[t]);
        float f[12];
        const float* car = g_car + (size_t)b*NRC*HW + pix;
        #pragma unroll
        for (int r = 0; r < NRC; r++) f[r] = car[(size_t)r*HW] * ss;
        f[8]  = ss;
        f[9]  = cta * ss;
        f[10] = sta * ss;
        f[11] = cvt * ss;
        float* ho = g_h + (size_t)b*NRC*HW + pix;
        #pragma unroll
        for (int r = 0; r < NRC; r++){
            float a = b1s[r];
            #pragma unroll
            for (int j = 0; j < 12; j++) a = fmaf(w1s[r*12+j], f[j], a);
            ho[(size_t)r*HW] = geluf(a);
        }
    }
}

// ---------------- K8: pure expansion h(8) -> 768; fc-half per block, 4 warps x 96 fc, 4 px/thread ----------------
__global__ __launch_bounds__(128) void k8_out(const float* __restrict__ w2,
                                              const float* __restrict__ b2,
                                              float* __restrict__ out){
    extern __shared__ ull sh[];
    ull*   w2p = sh;                     // 3072 packed (w,w) — this block's fc half
    float* b2s = (float*)(sh + 3072);    // 384
    int blk = blockIdx.x;                // 512 blocks = 256 pixel-groups x 2 fc halves
    int hsel = blk & 1, pgall = blk >> 1;
    int b = pgall >> 5, pgi = pgall & 31;
    const float* w2h = w2 + (size_t)hsel*384*8;
    for (int i = threadIdx.x; i < 3072; i += 128){ float v = w2h[i]; w2p[i] = pack2(v, v); }
    for (int i = threadIdx.x; i < 384; i += 128) b2s[i] = b2[hsel*384 + i];
    __syncthreads();

    int wp = threadIdx.x >> 5, lane = threadIdx.x & 31;
    int p = (pgi*32 + lane) << 2;        // pixel quad
    ull hl[NRC], hh[NRC];
    const float* hbase = g_h + (size_t)b*NRC*HW + p;
    #pragma unroll
    for (int r = 0; r < NRC; r++){
        float4 hv = *(const float4*)(hbase + (size_t)r*HW);
        hl[r] = pack2(hv.x, hv.y);
        hh[r] = pack2(hv.z, hv.w);
    }
    float* o = out + (size_t)b*NFC*HW + (size_t)(hsel*384)*HW + p;
    int fc0 = wp * 96;
    #pragma unroll 2
    for (int j = 0; j < 96; j++){
        int fc = fc0 + j;                // local within half
        float bb = b2s[fc];
        ull accl = pack2(bb, bb);
        ull acch = accl;
        const ulonglong2* wr = (const ulonglong2*)(w2p + fc*8);
        #pragma unroll
        for (int q = 0; q < 4; q++){
            ulonglong2 wv = wr[q];
            accl = fma2(wv.x, hl[q*2],   accl);
            acch = fma2(wv.x, hh[q*2],   acch);
            accl = fma2(wv.y, hl[q*2+1], accl);
            acch = fma2(wv.y, hh[q*2+1], acch);
        }
        float4 v;
        unpack2(accl, v.x, v.y);
        unpack2(acch, v.z, v.w);
        *(float4*)(o + (size_t)fc*HW) = v;
    }
}

// ---------------- host ----------------
extern "C" void kernel_launch(void* const* d_in, const int* in_sizes, int n_in,
                              void* d_out, int out_size){
    const float* fm    = (const float*)d_in[0];
    const float* theta = (const float*)d_in[1];
    const float* len   = (const float*)d_in[2];
    const float* wid   = (const float*)d_in[3];
    const float* curv  = (const float*)d_in[4];
    const float* alpha = (const float*)d_in[5];
    const float* obj   = (const float*)d_in[6];
    const float* plog  = (const float*)d_in[7];
    const float* fp1w  = (const float*)d_in[8];
    const float* fp1b  = (const float*)d_in[9];
    const float* fp2w  = (const float*)d_in[10];
    const float* fp2b  = (const float*)d_in[11];
    const float* pm1w  = (const float*)d_in[12];
    const float* pm1b  = (const float*)d_in[13];
    const float* pm2w  = (const float*)d_in[14];
    const float* pm2b  = (const float*)d_in[15];
    const float* pdel  = (const float*)d_in[16];

    cudaFuncSetAttribute(k1_gemm, cudaFuncAttributeMaxDynamicSharedMemorySize, 41216);
    cudaFuncSetAttribute(k8_out,  cudaFuncAttributeMaxDynamicSharedMemorySize, 26112);

    k1_gemm<<<512,256,41216>>>(fm, fp1w, fp1b, pdel);
    k23_conv<<<128,512>>>(fp2w, fp2b);
    k57_main<<<256,256>>>(theta, len, wid, plog, obj, alpha, curv, pm1w, pm1b);
    k8_out<<<512,128,26112>>>(pm2w, pm2b, (float*)d_out);
}